// round 5
// baseline (speedup 1.0000x reference)
#include <cuda_runtime.h>
#include <cuda_fp16.h>
#include <cstdint>

#define MAXN 8192
#define HD 64
#define SLOTS 32
#define EMB_MAX (50000 * HD)
#define BLKS 296
#define WPB 8
#define TW (BLKS * WPB)
#define GCH 128   // gather chunk rows

typedef unsigned long long u64;

// packed f32x2 helpers (ptxas never auto-emits these)
#define FFMA2(d, a, b, c) \
    asm("fma.rn.f32x2 %0, %1, %2, %3;" : "=l"(d) : "l"(a), "l"(b), "l"(c))
#define ADDF2(d, a, b) \
    asm("add.rn.f32x2 %0, %1, %2;" : "=l"(d) : "l"(a), "l"(b))
#define PACKF2(d, lo, hi) \
    asm("mov.b64 %0, {%1, %2};" : "=l"(d) : "f"(lo), "f"(hi))
#define UNPKF2(lo, hi, s) \
    asm("mov.b64 {%0, %1}, %2;" : "=f"(lo), "=f"(hi) : "l"(s))

// ---------------- static device scratch ----------------
__device__ __half g_embh[EMB_MAX];
__device__ float g_h[MAXN * HD];
__device__ int g_wr[MAXN];
__device__ int g_cnt[MAXN];
__device__ int g_buck[MAXN * SLOTS];
__device__ volatile int g_ready[MAXN];
__device__ unsigned g_max[HD];
__device__ unsigned g_done;

// ---------------- prep: fp16 embedding conversion + state reset ----------------
__global__ void prep_kernel(const float* __restrict__ emb, const int* __restrict__ tree,
                            int n_steps, int emb_total) {
    int t = blockIdx.x * blockDim.x + threadIdx.x;
    int e = t * 4;
    if (e + 3 < emb_total) {
        float4 f = *reinterpret_cast<const float4*>(emb + e);
        *reinterpret_cast<__half2*>(g_embh + e) = __floats2half2_rn(f.x, f.y);
        *reinterpret_cast<__half2*>(g_embh + e + 2) = __floats2half2_rn(f.z, f.w);
    }
    if (t < n_steps) {
        g_wr[t] = tree[2 * t + 1];
        g_ready[t] = 0;
    }
    if (t < MAXN) g_cnt[t] = 0;
    if (t < HD) g_max[t] = 0u;
    if (t == 0) g_done = 0u;
}

// ---------------- bucket fill: writes per node ----------------
__global__ void fill_kernel(const int* __restrict__ tree, int n_steps) {
    int i = blockIdx.x * blockDim.x + threadIdx.x;
    if (i >= n_steps) return;
    int v = tree[2 * i + 1];
    int s = atomicAdd(&g_cnt[v], 1);
    if (s < SLOTS) g_buck[v * SLOTS + s] = i;
}

// ---------------- gather one 128-row chunk (HFMA2 inner, fp32 flush per 4 rows) ----------------
__device__ __forceinline__ void gather_chunk(const float* __restrict__ xwr,
                                             const int* __restrict__ xir,
                                             int r0, int rl, int rg, float acc[8]) {
#pragma unroll 2
    for (int rr = 0; rr < GCH; rr += 16) {
        int rbase = r0 + rr + 4 * rg;
        float4 w4 = __ldg(reinterpret_cast<const float4*>(xwr + rbase));
        int4 i4 = __ldg(reinterpret_cast<const int4*>(xir + rbase));
        uint4 u0 = __ldg(reinterpret_cast<const uint4*>(g_embh + (size_t)i4.x * HD + rl * 8));
        uint4 u1 = __ldg(reinterpret_cast<const uint4*>(g_embh + (size_t)i4.y * HD + rl * 8));
        uint4 u2 = __ldg(reinterpret_cast<const uint4*>(g_embh + (size_t)i4.z * HD + rl * 8));
        uint4 u3 = __ldg(reinterpret_cast<const uint4*>(g_embh + (size_t)i4.w * HD + rl * 8));

        __half2 wh = __float2half2_rn(w4.x);
        __half2 a0 = __hmul2(wh, *reinterpret_cast<__half2*>(&u0.x));
        __half2 a1 = __hmul2(wh, *reinterpret_cast<__half2*>(&u0.y));
        __half2 a2 = __hmul2(wh, *reinterpret_cast<__half2*>(&u0.z));
        __half2 a3 = __hmul2(wh, *reinterpret_cast<__half2*>(&u0.w));
        wh = __float2half2_rn(w4.y);
        a0 = __hfma2(wh, *reinterpret_cast<__half2*>(&u1.x), a0);
        a1 = __hfma2(wh, *reinterpret_cast<__half2*>(&u1.y), a1);
        a2 = __hfma2(wh, *reinterpret_cast<__half2*>(&u1.z), a2);
        a3 = __hfma2(wh, *reinterpret_cast<__half2*>(&u1.w), a3);
        wh = __float2half2_rn(w4.z);
        a0 = __hfma2(wh, *reinterpret_cast<__half2*>(&u2.x), a0);
        a1 = __hfma2(wh, *reinterpret_cast<__half2*>(&u2.y), a1);
        a2 = __hfma2(wh, *reinterpret_cast<__half2*>(&u2.z), a2);
        a3 = __hfma2(wh, *reinterpret_cast<__half2*>(&u2.w), a3);
        wh = __float2half2_rn(w4.w);
        a0 = __hfma2(wh, *reinterpret_cast<__half2*>(&u3.x), a0);
        a1 = __hfma2(wh, *reinterpret_cast<__half2*>(&u3.y), a1);
        a2 = __hfma2(wh, *reinterpret_cast<__half2*>(&u3.z), a2);
        a3 = __hfma2(wh, *reinterpret_cast<__half2*>(&u3.w), a3);

        float2 f;
        f = __half22float2(a0); acc[0] += f.x; acc[1] += f.y;
        f = __half22float2(a1); acc[2] += f.x; acc[3] += f.y;
        f = __half22float2(a2); acc[4] += f.x; acc[5] += f.y;
        f = __half22float2(a3); acc[6] += f.x; acc[7] += f.y;
    }
}

// ---------------- fused gather + GRU dataflow (one step per warp, pipelined) ----------------
__global__ void __launch_bounds__(256, 2)
fused_kernel(const float* __restrict__ xw, const int* __restrict__ xi,
             const int* __restrict__ tree,
             const float* __restrict__ Wz, const float* __restrict__ Uz,
             const float* __restrict__ bz,
             const float* __restrict__ Wr, const float* __restrict__ Ur,
             const float* __restrict__ br,
             const float* __restrict__ Wh, const float* __restrict__ Uh,
             const float* __restrict__ bh,
             const int* __restrict__ np_ptr, int L, int n_steps,
             float* __restrict__ out) {
    extern __shared__ float sm[];
    float* sWzr = sm;             // [k*128 + 4l + {Wz2l,Wz2l+1,Wr2l,Wr2l+1}]
    float* sWh2 = sm + 8192;      // [kp*128 + 4l + {Wh[2l][2kp],Wh[2l+1][2kp],Wh[2l][2kp+1],Wh[2l+1][2kp+1]}]
    float* sUzr = sm + 12288;
    float* sUh2 = sm + 20480;
    float* sXe = sm + 24576;      // per-warp 64
    float* sP  = sm + 25088;
    float* sPr = sm + 25600;

    int tid = threadIdx.x;
    int wid = tid >> 5, l = tid & 31;
    int rl = l & 7, rg = l >> 3;

    // pack weight matrices into interleaved smem layouts
    for (int t = tid; t < 8192; t += 256) {
        int k = t >> 7, q = t & 127, lane = q >> 2, c = q & 3;
        int j = 2 * lane + (c & 1);
        sWzr[t] = (c < 2 ? Wz : Wr)[j * 64 + k];
        sUzr[t] = (c < 2 ? Uz : Ur)[j * 64 + k];
    }
    for (int t = tid; t < 4096; t += 256) {
        int kp = t >> 7, q = t & 127, lane = q >> 2, c = q & 3;
        int j = 2 * lane + (c & 1);
        int k = 2 * kp + (c >> 1);
        sWh2[t] = Wh[j * 64 + k];
        sUh2[t] = Uh[j * 64 + k];
    }
    float2 bz2 = reinterpret_cast<const float2*>(bz)[l];
    float2 br2 = reinterpret_cast<const float2*>(br)[l];
    float2 bh2 = reinterpret_cast<const float2*>(bh)[l];
    int np1 = np_ptr[0] - 1;
    __syncthreads();

    const ulonglong2* Wzr8 = reinterpret_cast<const ulonglong2*>(sWzr);
    const ulonglong2* Wh8  = reinterpret_cast<const ulonglong2*>(sWh2);
    const ulonglong2* Uzr8 = reinterpret_cast<const ulonglong2*>(sUzr);
    const ulonglong2* Uh8  = reinterpret_cast<const ulonglong2*>(sUh2);
    float* xe_w = sXe + wid * 64;
    float* p_w  = sP + wid * 64;
    float* pr_w = sPr + wid * 64;
    float2 lm = make_float2(-3.402823466e38f, -3.402823466e38f);

    // preamble: gather first owned step
    int i0 = blockIdx.x * WPB + wid;
    float acc[8] = {0.f, 0.f, 0.f, 0.f, 0.f, 0.f, 0.f, 0.f};
    if (i0 < n_steps) {
        const float* xwr = xw + (size_t)i0 * L;
        const int* xir = xi + (size_t)i0 * L;
        for (int r0 = 0; r0 < L; r0 += GCH) gather_chunk(xwr, xir, r0, rl, rg, acc);
    }

    for (int i = i0; i < n_steps; i += TW) {
        int inext = i + TW;
        bool has_next = (inext < n_steps);
        const float* xwrN = xw + (size_t)inext * L;
        const int* xirN = xi + (size_t)inext * L;

        // ---- reduce acc -> xe_w (sum over rg groups) ----
#pragma unroll
        for (int u = 0; u < 8; u++) {
            acc[u] += __shfl_xor_sync(0xffffffffu, acc[u], 8);
            acc[u] += __shfl_xor_sync(0xffffffffu, acc[u], 16);
        }
        if (rg == 0) {
#pragma unroll
            for (int u = 0; u < 8; u++) xe_w[rl * 8 + u] = acc[u];
        }
        __syncwarp();
#pragma unroll
        for (int u = 0; u < 8; u++) acc[u] = 0.f;

        // ---- dep(i): last j<i writing node tree[i,0] ----
        int v = tree[2 * i];
        int c = g_cnt[v];
        int d = -1;
        if (c <= SLOTS) {
            if (l < c) {
                int j = g_buck[v * SLOTS + l];
                if (j < i) d = j;
            }
        } else {
            if (l == 0)
                for (int j = i - 1; j >= 0; --j)
                    if (g_wr[j] == v) { d = j; break; }
        }
        d = __reduce_max_sync(0xffffffffu, d);

        // ---- W matvecs (pre-wait): a = W xe + b, packed f32x2 ----
        u64 aZ0, aZ1, aR0, aR1, aH0, aH1;
        PACKF2(aZ0, bz2.x, bz2.y); PACKF2(aZ1, 0.f, 0.f);
        PACKF2(aR0, br2.x, br2.y); PACKF2(aR1, 0.f, 0.f);
        PACKF2(aH0, bh2.x, bh2.y); PACKF2(aH1, 0.f, 0.f);
#pragma unroll
        for (int k = 0; k < 64; k += 2) {
            float2 x = *reinterpret_cast<const float2*>(&xe_w[k]);
            u64 xx0, xx1;
            PACKF2(xx0, x.x, x.x); PACKF2(xx1, x.y, x.y);
            ulonglong2 m0 = Wzr8[k * 32 + l];
            ulonglong2 m1 = Wzr8[(k + 1) * 32 + l];
            FFMA2(aZ0, m0.x, xx0, aZ0); FFMA2(aR0, m0.y, xx0, aR0);
            FFMA2(aZ1, m1.x, xx1, aZ1); FFMA2(aR1, m1.y, xx1, aR1);
            ulonglong2 mh = Wh8[(k >> 1) * 32 + l];
            FFMA2(aH0, mh.x, xx0, aH0); FFMA2(aH1, mh.y, xx1, aH1);
        }
        u64 azP, arP, ahP;
        ADDF2(azP, aZ0, aZ1);
        ADDF2(arP, aR0, aR1);
        ADDF2(ahP, aH0, aH1);

        // ---- probe dep; gather next step's chunks while not ready ----
        int pr_r0 = 0;
        float2 p2;
        if (d >= 0) {
            int rdy = (l == 0) ? g_ready[d] : 0;
            rdy = __shfl_sync(0xffffffffu, rdy, 0);
            while (!rdy) {
                if (has_next && pr_r0 < L) {
                    gather_chunk(xwrN, xirN, pr_r0, rl, rg, acc);
                    pr_r0 += GCH;
                } else {
                    if (l == 0) {
                        int cnt = 0;
                        while (g_ready[d] == 0)
                            if (((++cnt) & 31) == 0) __nanosleep(64);
                    }
                    break;
                }
                rdy = (l == 0) ? g_ready[d] : 0;
                rdy = __shfl_sync(0xffffffffu, rdy, 0);
            }
            __syncwarp();
            __threadfence();   // acquire: order p load after flag observation
            p2 = __ldcg(reinterpret_cast<const float2*>(g_h + (size_t)d * HD) + l);
        } else {
            p2 = make_float2(0.f, 0.f);
        }
        *reinterpret_cast<float2*>(&p_w[2 * l]) = p2;
        __syncwarp();

        // ---- U z/r matvec (packed, init from W result) ----
        u64 sZ0 = azP, sR0 = arP, sZ1, sR1;
        PACKF2(sZ1, 0.f, 0.f); PACKF2(sR1, 0.f, 0.f);
#pragma unroll
        for (int k = 0; k < 64; k += 2) {
            float2 x = *reinterpret_cast<const float2*>(&p_w[k]);
            u64 xx0, xx1;
            PACKF2(xx0, x.x, x.x); PACKF2(xx1, x.y, x.y);
            ulonglong2 m0 = Uzr8[k * 32 + l];
            ulonglong2 m1 = Uzr8[(k + 1) * 32 + l];
            FFMA2(sZ0, m0.x, xx0, sZ0); FFMA2(sR0, m0.y, xx0, sR0);
            FFMA2(sZ1, m1.x, xx1, sZ1); FFMA2(sR1, m1.y, xx1, sR1);
        }
        ADDF2(sZ0, sZ0, sZ1);
        ADDF2(sR0, sR0, sR1);
        float zlo, zhi, rlo, rhi;
        UNPKF2(zlo, zhi, sZ0);
        UNPKF2(rlo, rhi, sR0);
        float2 z2, r2;
        z2.x = fminf(fmaxf(0.2f * zlo + 0.5f, 0.f), 1.f);
        z2.y = fminf(fmaxf(0.2f * zhi + 0.5f, 0.f), 1.f);
        r2.x = fminf(fmaxf(0.2f * rlo + 0.5f, 0.f), 1.f);
        r2.y = fminf(fmaxf(0.2f * rhi + 0.5f, 0.f), 1.f);
        *reinterpret_cast<float2*>(&pr_w[2 * l]) =
            make_float2(p2.x * r2.x, p2.y * r2.y);
        __syncwarp();

        // ---- Uh matvec (packed) ----
        u64 sH0 = ahP, sH1;
        PACKF2(sH1, 0.f, 0.f);
#pragma unroll
        for (int kp = 0; kp < 32; kp++) {
            float2 x = *reinterpret_cast<const float2*>(&pr_w[2 * kp]);
            u64 xx0, xx1;
            PACKF2(xx0, x.x, x.x); PACKF2(xx1, x.y, x.y);
            ulonglong2 m = Uh8[kp * 32 + l];
            FFMA2(sH0, m.x, xx0, sH0); FFMA2(sH1, m.y, xx1, sH1);
        }
        ADDF2(sH0, sH0, sH1);
        float hlo, hhi;
        UNPKF2(hlo, hhi, sH0);
        float2 h2;
        h2.x = z2.x * p2.x + (1.f - z2.x) * tanhf(hlo);
        h2.y = z2.y * p2.y + (1.f - z2.y) * tanhf(hhi);

        __stcg(reinterpret_cast<float2*>(g_h + (size_t)i * HD) + l, h2);
        if (i >= np1) {
            lm.x = fmaxf(lm.x, h2.x);
            lm.y = fmaxf(lm.y, h2.y);
        }
        __threadfence();          // release h stores
        __syncwarp();
        if (l == 0) g_ready[i] = 1;

        // ---- finish remaining gather chunks for next step ----
        while (has_next && pr_r0 < L) {
            gather_chunk(xwrN, xirN, pr_r0, rl, rg, acc);
            pr_r0 += GCH;
        }
    }

    // fold local max, then last block writes output
    unsigned ux = __float_as_uint(lm.x);
    ux = (ux & 0x80000000u) ? ~ux : (ux | 0x80000000u);
    unsigned uy = __float_as_uint(lm.y);
    uy = (uy & 0x80000000u) ? ~uy : (uy | 0x80000000u);
    atomicMax(&g_max[2 * l], ux);
    atomicMax(&g_max[2 * l + 1], uy);
    __threadfence();
    __syncthreads();
    __shared__ unsigned s_last;
    if (tid == 0) s_last = (atomicAdd(&g_done, 1u) == BLKS - 1) ? 1u : 0u;
    __syncthreads();
    if (s_last && tid < HD) {
        unsigned u = atomicMax(&g_max[tid], 0u);   // atomic read of final value
        unsigned b = (u & 0x80000000u) ? (u & 0x7fffffffu) : ~u;
        out[tid] = __uint_as_float(b);
    }
}

// ---------------- launch ----------------
extern "C" void kernel_launch(void* const* d_in, const int* in_sizes, int n_in,
                              void* d_out, int out_size) {
    const float* xw = (const float*)d_in[0];
    const int* xi = (const int*)d_in[1];
    const int* tree = (const int*)d_in[2];
    const int* np = (const int*)d_in[3];
    const float* emb = (const float*)d_in[4];
    const float* Wz = (const float*)d_in[5];
    const float* Uz = (const float*)d_in[6];
    const float* bz = (const float*)d_in[7];
    const float* Wr = (const float*)d_in[8];
    const float* Ur = (const float*)d_in[9];
    const float* br = (const float*)d_in[10];
    const float* Wh = (const float*)d_in[11];
    const float* Uh = (const float*)d_in[12];
    const float* bh = (const float*)d_in[13];

    int N = in_sizes[2] / 2;      // tree is [N,2]
    int L = in_sizes[0] / N;      // x_word is [N,L]
    int n_steps = N - 1;
    int emb_total = in_sizes[4];  // V*H floats

    static int smem_set = 0;
    const int SMEM_BYTES = (24576 + 1536) * 4;  // 104448
    if (!smem_set) {
        cudaFuncSetAttribute(fused_kernel,
                             cudaFuncAttributeMaxDynamicSharedMemorySize, SMEM_BYTES);
        smem_set = 1;
    }

    int prep_threads = (emb_total + 3) / 4;
    if (prep_threads < MAXN) prep_threads = MAXN;
    prep_kernel<<<(prep_threads + 255) / 256, 256>>>(emb, tree, n_steps, emb_total);
    fill_kernel<<<(n_steps + 255) / 256, 256>>>(tree, n_steps);
    fused_kernel<<<BLKS, 256, SMEM_BYTES>>>(xw, xi, tree, Wz, Uz, bz, Wr, Ur, br,
                                            Wh, Uh, bh, np, L, n_steps,
                                            (float*)d_out);
}

// round 6
// speedup vs baseline: 1.0344x; 1.0344x over previous
#include <cuda_runtime.h>
#include <cuda_fp16.h>
#include <cstdint>

#define MAXN 8192
#define HD 64
#define SLOTS 32
#define EMB_MAX (50000 * HD)
#define BLKS 296
#define WPB 8
#define TW (BLKS * WPB)
#define GCH 128   // gather chunk rows

// ---------------- static device scratch ----------------
__device__ __half g_embh[EMB_MAX];
__device__ float g_h[MAXN * HD];
__device__ int g_wr[MAXN];
__device__ int g_cnt[MAXN];
__device__ int g_buck[MAXN * SLOTS];
__device__ volatile int g_ready[MAXN];
__device__ unsigned g_max[HD];
__device__ unsigned g_done;

// ---------------- prep: fp16 embedding conversion + state reset ----------------
__global__ void prep_kernel(const float* __restrict__ emb, const int* __restrict__ tree,
                            int n_steps, int emb_total) {
    int t = blockIdx.x * blockDim.x + threadIdx.x;
    int e = t * 8;
    if (e + 7 < emb_total) {
        float4 f0 = *reinterpret_cast<const float4*>(emb + e);
        float4 f1 = *reinterpret_cast<const float4*>(emb + e + 4);
        *reinterpret_cast<__half2*>(g_embh + e)     = __floats2half2_rn(f0.x, f0.y);
        *reinterpret_cast<__half2*>(g_embh + e + 2) = __floats2half2_rn(f0.z, f0.w);
        *reinterpret_cast<__half2*>(g_embh + e + 4) = __floats2half2_rn(f1.x, f1.y);
        *reinterpret_cast<__half2*>(g_embh + e + 6) = __floats2half2_rn(f1.z, f1.w);
    }
    if (t < n_steps) {
        g_wr[t] = tree[2 * t + 1];
        g_ready[t] = 0;
    }
    if (t < MAXN) g_cnt[t] = 0;
    if (t < HD) g_max[t] = 0u;
    if (t == 0) g_done = 0u;
}

// ---------------- bucket fill: writes per node ----------------
__global__ void fill_kernel(const int* __restrict__ tree, int n_steps) {
    int i = blockIdx.x * blockDim.x + threadIdx.x;
    if (i >= n_steps) return;
    int v = tree[2 * i + 1];
    int s = atomicAdd(&g_cnt[v], 1);
    if (s < SLOTS) g_buck[v * SLOTS + s] = i;
}

// ---------------- gather one 128-row chunk, index-staged for high MLP ----------------
__device__ __forceinline__ void gather_chunk(const float* __restrict__ xwr,
                                             const int* __restrict__ xir,
                                             int r0, int rl, int rg, float acc[8]) {
#pragma unroll
    for (int half = 0; half < 2; half++) {
        int hb = r0 + half * 64 + 4 * rg;
        // stage all index/weight loads for this 64-row half (independent -> batched)
        float4 w[4];
        int4 ix[4];
#pragma unroll
        for (int g = 0; g < 4; g++) {
            w[g]  = __ldg(reinterpret_cast<const float4*>(xwr + hb + 16 * g));
            ix[g] = __ldg(reinterpret_cast<const int4*>(xir + hb + 16 * g));
        }
        // emb loads: all 16 addresses ready up front -> deep LDG batching
#pragma unroll
        for (int g = 0; g < 4; g++) {
            uint4 u0 = __ldg(reinterpret_cast<const uint4*>(g_embh + (size_t)ix[g].x * HD + rl * 8));
            uint4 u1 = __ldg(reinterpret_cast<const uint4*>(g_embh + (size_t)ix[g].y * HD + rl * 8));
            uint4 u2 = __ldg(reinterpret_cast<const uint4*>(g_embh + (size_t)ix[g].z * HD + rl * 8));
            uint4 u3 = __ldg(reinterpret_cast<const uint4*>(g_embh + (size_t)ix[g].w * HD + rl * 8));
#define ACCUM(U, W)                                                              \
            {                                                                    \
                float2 f0 = __half22float2(*reinterpret_cast<__half2*>(&U.x));  \
                float2 f1 = __half22float2(*reinterpret_cast<__half2*>(&U.y));  \
                float2 f2 = __half22float2(*reinterpret_cast<__half2*>(&U.z));  \
                float2 f3 = __half22float2(*reinterpret_cast<__half2*>(&U.w));  \
                acc[0] = fmaf(W, f0.x, acc[0]); acc[1] = fmaf(W, f0.y, acc[1]); \
                acc[2] = fmaf(W, f1.x, acc[2]); acc[3] = fmaf(W, f1.y, acc[3]); \
                acc[4] = fmaf(W, f2.x, acc[4]); acc[5] = fmaf(W, f2.y, acc[5]); \
                acc[6] = fmaf(W, f3.x, acc[6]); acc[7] = fmaf(W, f3.y, acc[7]); \
            }
            ACCUM(u0, w[g].x) ACCUM(u1, w[g].y) ACCUM(u2, w[g].z) ACCUM(u3, w[g].w)
#undef ACCUM
        }
    }
}

// ---------------- fused gather + GRU dataflow (one step per warp, pipelined) ----------------
__global__ void __launch_bounds__(256, 2)
fused_kernel(const float* __restrict__ xw, const int* __restrict__ xi,
             const int* __restrict__ tree,
             const float* __restrict__ Wz, const float* __restrict__ Uz,
             const float* __restrict__ bz,
             const float* __restrict__ Wr, const float* __restrict__ Ur,
             const float* __restrict__ br,
             const float* __restrict__ Wh, const float* __restrict__ Uh,
             const float* __restrict__ bh,
             const int* __restrict__ np_ptr, int L, int n_steps,
             float* __restrict__ out) {
    extern __shared__ float sm[];
    float* sWzr = sm;             // [k*128 + 4l + {Wz2l,Wz2l+1,Wr2l,Wr2l+1}]
    float* sWh2 = sm + 8192;      // [kp*128 + 4l + {Wh[2l][2kp],Wh[2l+1][2kp],Wh[2l][2kp+1],Wh[2l+1][2kp+1]}]
    float* sUzr = sm + 12288;
    float* sUh2 = sm + 20480;
    float* sXe = sm + 24576;      // per-warp 64
    float* sP  = sm + 25088;
    float* sPr = sm + 25600;

    int tid = threadIdx.x;
    int wid = tid >> 5, l = tid & 31;
    int rl = l & 7, rg = l >> 3;

    // pack weight matrices into interleaved smem layouts
    for (int t = tid; t < 8192; t += 256) {
        int k = t >> 7, q = t & 127, lane = q >> 2, c = q & 3;
        int j = 2 * lane + (c & 1);
        sWzr[t] = (c < 2 ? Wz : Wr)[j * 64 + k];
        sUzr[t] = (c < 2 ? Uz : Ur)[j * 64 + k];
    }
    for (int t = tid; t < 4096; t += 256) {
        int kp = t >> 7, q = t & 127, lane = q >> 2, c = q & 3;
        int j = 2 * lane + (c & 1);
        int k = 2 * kp + (c >> 1);
        sWh2[t] = Wh[j * 64 + k];
        sUh2[t] = Uh[j * 64 + k];
    }
    float2 bz2 = reinterpret_cast<const float2*>(bz)[l];
    float2 br2 = reinterpret_cast<const float2*>(br)[l];
    float2 bh2 = reinterpret_cast<const float2*>(bh)[l];
    int np1 = np_ptr[0] - 1;
    __syncthreads();

    const float4* Wzr4 = reinterpret_cast<const float4*>(sWzr);
    const float4* Wh4  = reinterpret_cast<const float4*>(sWh2);
    const float4* Uzr4 = reinterpret_cast<const float4*>(sUzr);
    const float4* Uh4  = reinterpret_cast<const float4*>(sUh2);
    float* xe_w = sXe + wid * 64;
    float* p_w  = sP + wid * 64;
    float* pr_w = sPr + wid * 64;
    float2 lm = make_float2(-3.402823466e38f, -3.402823466e38f);

    // preamble: gather first owned step
    int i0 = blockIdx.x * WPB + wid;
    float acc[8] = {0.f, 0.f, 0.f, 0.f, 0.f, 0.f, 0.f, 0.f};
    if (i0 < n_steps) {
        const float* xwr = xw + (size_t)i0 * L;
        const int* xir = xi + (size_t)i0 * L;
        for (int r0 = 0; r0 < L; r0 += GCH) gather_chunk(xwr, xir, r0, rl, rg, acc);
    }

    for (int i = i0; i < n_steps; i += TW) {
        int inext = i + TW;
        bool has_next = (inext < n_steps);
        const float* xwrN = xw + (size_t)inext * L;
        const int* xirN = xi + (size_t)inext * L;

        // ---- reduce acc -> xe_w (sum over rg groups) ----
#pragma unroll
        for (int u = 0; u < 8; u++) {
            acc[u] += __shfl_xor_sync(0xffffffffu, acc[u], 8);
            acc[u] += __shfl_xor_sync(0xffffffffu, acc[u], 16);
        }
        if (rg == 0) {
#pragma unroll
            for (int u = 0; u < 8; u++) xe_w[rl * 8 + u] = acc[u];
        }
        __syncwarp();
#pragma unroll
        for (int u = 0; u < 8; u++) acc[u] = 0.f;

        // ---- dep(i): last j<i writing node tree[i,0] ----
        int v = tree[2 * i];
        int c = g_cnt[v];
        int d = -1;
        if (c <= SLOTS) {
            if (l < c) {
                int j = g_buck[v * SLOTS + l];
                if (j < i) d = j;
            }
        } else {
            if (l == 0)
                for (int j = i - 1; j >= 0; --j)
                    if (g_wr[j] == v) { d = j; break; }
        }
        d = __reduce_max_sync(0xffffffffu, d);

        // ---- W matvecs (pre-wait): a = W xe + b ----
        float4 wzrA = make_float4(bz2.x, bz2.y, br2.x, br2.y);
        float4 wzrB = make_float4(0.f, 0.f, 0.f, 0.f);
        float2 whA = bh2, whB = make_float2(0.f, 0.f);
#pragma unroll
        for (int k = 0; k < 64; k += 2) {
            float2 x = *reinterpret_cast<const float2*>(&xe_w[k]);
            float4 m0 = Wzr4[k * 32 + l];
            float4 m1 = Wzr4[(k + 1) * 32 + l];
            wzrA.x = fmaf(m0.x, x.x, wzrA.x); wzrA.y = fmaf(m0.y, x.x, wzrA.y);
            wzrA.z = fmaf(m0.z, x.x, wzrA.z); wzrA.w = fmaf(m0.w, x.x, wzrA.w);
            wzrB.x = fmaf(m1.x, x.y, wzrB.x); wzrB.y = fmaf(m1.y, x.y, wzrB.y);
            wzrB.z = fmaf(m1.z, x.y, wzrB.z); wzrB.w = fmaf(m1.w, x.y, wzrB.w);
            float4 mh = Wh4[(k >> 1) * 32 + l];
            whA.x = fmaf(mh.x, x.x, whA.x); whA.y = fmaf(mh.y, x.x, whA.y);
            whB.x = fmaf(mh.z, x.y, whB.x); whB.y = fmaf(mh.w, x.y, whB.y);
        }
        float2 az2 = make_float2(wzrA.x + wzrB.x, wzrA.y + wzrB.y);
        float2 ar2 = make_float2(wzrA.z + wzrB.z, wzrA.w + wzrB.w);
        float2 ah2 = make_float2(whA.x + whB.x, whA.y + whB.y);

        // ---- probe dep; gather next step's chunks while not ready ----
        int pr_r0 = 0;
        float2 p2;
        if (d >= 0) {
            int rdy = (l == 0) ? g_ready[d] : 0;
            rdy = __shfl_sync(0xffffffffu, rdy, 0);
            while (!rdy) {
                if (has_next && pr_r0 < L) {
                    gather_chunk(xwrN, xirN, pr_r0, rl, rg, acc);
                    pr_r0 += GCH;
                } else {
                    if (l == 0) {
                        int cnt = 0;
                        while (g_ready[d] == 0)
                            if (((++cnt) & 31) == 0) __nanosleep(64);
                    }
                    break;
                }
                rdy = (l == 0) ? g_ready[d] : 0;
                rdy = __shfl_sync(0xffffffffu, rdy, 0);
            }
            __syncwarp();
            __threadfence();   // acquire: order p load after flag observation
            p2 = __ldcg(reinterpret_cast<const float2*>(g_h + (size_t)d * HD) + l);
        } else {
            p2 = make_float2(0.f, 0.f);
        }
        *reinterpret_cast<float2*>(&p_w[2 * l]) = p2;
        __syncwarp();

        // ---- U z/r matvec ----
        float4 sA = make_float4(az2.x, az2.y, ar2.x, ar2.y);
        float4 sB = make_float4(0.f, 0.f, 0.f, 0.f);
#pragma unroll
        for (int k = 0; k < 64; k += 2) {
            float2 x = *reinterpret_cast<const float2*>(&p_w[k]);
            float4 m0 = Uzr4[k * 32 + l];
            float4 m1 = Uzr4[(k + 1) * 32 + l];
            sA.x = fmaf(m0.x, x.x, sA.x); sA.y = fmaf(m0.y, x.x, sA.y);
            sA.z = fmaf(m0.z, x.x, sA.z); sA.w = fmaf(m0.w, x.x, sA.w);
            sB.x = fmaf(m1.x, x.y, sB.x); sB.y = fmaf(m1.y, x.y, sB.y);
            sB.z = fmaf(m1.z, x.y, sB.z); sB.w = fmaf(m1.w, x.y, sB.w);
        }
        float2 z2, r2;
        z2.x = fminf(fmaxf(0.2f * (sA.x + sB.x) + 0.5f, 0.f), 1.f);
        z2.y = fminf(fmaxf(0.2f * (sA.y + sB.y) + 0.5f, 0.f), 1.f);
        r2.x = fminf(fmaxf(0.2f * (sA.z + sB.z) + 0.5f, 0.f), 1.f);
        r2.y = fminf(fmaxf(0.2f * (sA.w + sB.w) + 0.5f, 0.f), 1.f);
        *reinterpret_cast<float2*>(&pr_w[2 * l]) =
            make_float2(p2.x * r2.x, p2.y * r2.y);
        __syncwarp();

        // ---- Uh matvec ----
        float2 hA = ah2, hB = make_float2(0.f, 0.f);
#pragma unroll
        for (int kp = 0; kp < 32; kp++) {
            float2 x = *reinterpret_cast<const float2*>(&pr_w[2 * kp]);
            float4 m = Uh4[kp * 32 + l];
            hA.x = fmaf(m.x, x.x, hA.x); hA.y = fmaf(m.y, x.x, hA.y);
            hB.x = fmaf(m.z, x.y, hB.x); hB.y = fmaf(m.w, x.y, hB.y);
        }
        float2 h2;
        h2.x = z2.x * p2.x + (1.f - z2.x) * tanhf(hA.x + hB.x);
        h2.y = z2.y * p2.y + (1.f - z2.y) * tanhf(hA.y + hB.y);

        __stcg(reinterpret_cast<float2*>(g_h + (size_t)i * HD) + l, h2);
        if (i >= np1) {
            lm.x = fmaxf(lm.x, h2.x);
            lm.y = fmaxf(lm.y, h2.y);
        }
        __threadfence();          // release h stores
        __syncwarp();
        if (l == 0) g_ready[i] = 1;

        // ---- finish remaining gather chunks for next step ----
        while (has_next && pr_r0 < L) {
            gather_chunk(xwrN, xirN, pr_r0, rl, rg, acc);
            pr_r0 += GCH;
        }
    }

    // fold local max, then last block writes output
    unsigned ux = __float_as_uint(lm.x);
    ux = (ux & 0x80000000u) ? ~ux : (ux | 0x80000000u);
    unsigned uy = __float_as_uint(lm.y);
    uy = (uy & 0x80000000u) ? ~uy : (uy | 0x80000000u);
    atomicMax(&g_max[2 * l], ux);
    atomicMax(&g_max[2 * l + 1], uy);
    __threadfence();
    __syncthreads();
    __shared__ unsigned s_last;
    if (tid == 0) s_last = (atomicAdd(&g_done, 1u) == BLKS - 1) ? 1u : 0u;
    __syncthreads();
    if (s_last && tid < HD) {
        unsigned u = atomicMax(&g_max[tid], 0u);   // atomic read of final value
        unsigned b = (u & 0x80000000u) ? (u & 0x7fffffffu) : ~u;
        out[tid] = __uint_as_float(b);
    }
}

// ---------------- launch ----------------
extern "C" void kernel_launch(void* const* d_in, const int* in_sizes, int n_in,
                              void* d_out, int out_size) {
    const float* xw = (const float*)d_in[0];
    const int* xi = (const int*)d_in[1];
    const int* tree = (const int*)d_in[2];
    const int* np = (const int*)d_in[3];
    const float* emb = (const float*)d_in[4];
    const float* Wz = (const float*)d_in[5];
    const float* Uz = (const float*)d_in[6];
    const float* bz = (const float*)d_in[7];
    const float* Wr = (const float*)d_in[8];
    const float* Ur = (const float*)d_in[9];
    const float* br = (const float*)d_in[10];
    const float* Wh = (const float*)d_in[11];
    const float* Uh = (const float*)d_in[12];
    const float* bh = (const float*)d_in[13];

    int N = in_sizes[2] / 2;      // tree is [N,2]
    int L = in_sizes[0] / N;      // x_word is [N,L]
    int n_steps = N - 1;
    int emb_total = in_sizes[4];  // V*H floats

    static int smem_set = 0;
    const int SMEM_BYTES = (24576 + 1536) * 4;  // 104448
    if (!smem_set) {
        cudaFuncSetAttribute(fused_kernel,
                             cudaFuncAttributeMaxDynamicSharedMemorySize, SMEM_BYTES);
        smem_set = 1;
    }

    int prep_threads = (emb_total + 7) / 8;
    if (prep_threads < MAXN) prep_threads = MAXN;
    prep_kernel<<<(prep_threads + 255) / 256, 256>>>(emb, tree, n_steps, emb_total);
    fill_kernel<<<(n_steps + 255) / 256, 256>>>(tree, n_steps);
    fused_kernel<<<BLKS, 256, SMEM_BYTES>>>(xw, xi, tree, Wz, Uz, bz, Wr, Ur, br,
                                            Wh, Uh, bh, np, L, n_steps,
                                            (float*)d_out);
}